// round 15
// baseline (speedup 1.0000x reference)
#include <cuda_runtime.h>
#include <math.h>

#define BB 32
#define NN 64
#define KK 128
#define NPAIR (BB*NN*NN)
#define NNODE (BB*NN)

__device__ float g_rad[NPAIR*8];
__device__ float g_Y[NPAIR*8];
__device__ float g_mask[NPAIR];
__device__ float g_h1[NNODE*KK];
__device__ float g_s1[NNODE*KK];
__device__ float g_v1[NNODE*3*KK];
__device__ float g_s2[NNODE*KK];

__device__ __forceinline__ float siluf(float x) { return x / (1.0f + __expf(-x)); }

typedef unsigned long long u64;
__device__ __forceinline__ u64 pk2(float lo, float hi) {
    u64 r; asm("mov.b64 %0, {%1,%2};" : "=l"(r) : "f"(lo), "f"(hi)); return r;
}
__device__ __forceinline__ void fma2(u64& a, u64 x, u64 y) {
    asm("fma.rn.f32x2 %0, %1, %2, %3;" : "=l"(a) : "l"(x), "l"(y), "l"(a));
}
__device__ __forceinline__ float2 upk(u64 v) {
    float2 o; asm("mov.b64 {%0,%1}, %2;" : "=f"(o.x), "=f"(o.y) : "l"(v)); return o;
}

// ---------------- kernel 1: pairwise geometry ----------------
__global__ void k_geom(const float* __restrict__ frac, const float* __restrict__ cell)
{
    int idx = blockIdx.x * blockDim.x + threadIdx.x;
    if (idx >= NPAIR) return;
    int b = idx >> 12;
    int i = (idx >> 6) & 63;
    int j = idx & 63;
    const float* fi = frac + (b*NN + i)*3;
    const float* fj = frac + (b*NN + j)*3;
    float d0 = fi[0]-fj[0], d1 = fi[1]-fj[1], d2 = fi[2]-fj[2];
    d0 -= rintf(d0); d1 -= rintf(d1); d2 -= rintf(d2);
    const float* C = cell + b*9;
    float x = d0*C[0] + d1*C[3] + d2*C[6];
    float y = d0*C[1] + d1*C[4] + d2*C[7];
    float z = d0*C[2] + d1*C[5] + d2*C[8];
    float r2 = fmaxf(x*x + y*y + z*z, 1e-12f);
    float r = sqrtf(r2);
    bool m = (r < 5.0f) && (i != j);
    float mf = m ? 1.0f : 0.0f;
    float rs = m ? r : 1.0f;
    float inv = 1.0f / rs;
    float ux = x*inv*mf, uy = y*inv*mf, uz = z*inv*mf;
    float u = rs * 0.2f;
    float u2 = u*u, u4 = u2*u2, u5 = u4*u;
    float fc = 1.0f - 21.0f*u5 + 35.0f*u5*u - 15.0f*u5*u2;
    fc = (u < 1.0f) ? fc : 0.0f;
    float pref = 0.6324555320336759f * inv * fc * mf;
    float w = 0.6283185307179586f * rs;
    float* rp = g_rad + (size_t)idx*8;
    #pragma unroll
    for (int n = 1; n <= 8; ++n) rp[n-1] = pref * sinf((float)n * w);
    const float s3 = 1.7320508075688772f, s5 = 2.23606797749979f, s15 = 3.872983346207417f;
    float* Y = g_Y + (size_t)idx*8;
    Y[0] = s3*ux; Y[1] = s3*uy; Y[2] = s3*uz;
    Y[3] = s15*ux*uy;
    Y[4] = s15*uy*uz;
    Y[5] = 0.5f*s5*(3.0f*uz*uz - 1.0f);
    Y[6] = s15*ux*uz;
    Y[7] = 0.5f*s15*(ux*ux - uy*uy);
    g_mask[idx] = mf;
}

// ---------------- 64-wide dense layer (silu), 256 threads, 2j x 16h x 4c ----------------
// In: [64][ldi] smem (ldi mult of 4), Wsh: [CDIM][64] smem, Out: [64][64].
// thread t: jbase = t>>4 (0..15), h0 = (t&15)*4; 2 outer its cover j.
template<int CDIM>
__device__ __forceinline__ void dense_layer256(const float* __restrict__ In, int ldi,
                                               const float* __restrict__ Wsh,
                                               const float* __restrict__ bias,
                                               float* __restrict__ Out, int t)
{
    int jbase = t >> 4;          // 0..15
    int h0 = (t & 15) * 4;
    #pragma unroll 1
    for (int it = 0; it < 2; ++it) {
        int jA = jbase + 16*it;  // 0..31
        int jB = jA + 32;        // 32..63
        float a0 = bias[h0+0], a1 = bias[h0+1], a2 = bias[h0+2], a3 = bias[h0+3];
        float b0 = a0, b1 = a1, b2 = a2, b3 = a3;
        const float* inA = In + jA*ldi;
        const float* inB = In + jB*ldi;
        #pragma unroll 2
        for (int c = 0; c < CDIM; c += 4) {
            float4 av4 = *(const float4*)(inA + c);
            float4 bv4 = *(const float4*)(inB + c);
            float aarr[4] = {av4.x, av4.y, av4.z, av4.w};
            float barr[4] = {bv4.x, bv4.y, bv4.z, bv4.w};
            #pragma unroll
            for (int d = 0; d < 4; ++d) {
                float4 wv = *(const float4*)(Wsh + (c+d)*64 + h0);
                float av = aarr[d], bv = barr[d];
                a0 += av*wv.x; a1 += av*wv.y; a2 += av*wv.z; a3 += av*wv.w;
                b0 += bv*wv.x; b1 += bv*wv.y; b2 += bv*wv.z; b3 += bv*wv.w;
            }
        }
        float4 oA, oB;
        oA.x = siluf(a0); oA.y = siluf(a1); oA.z = siluf(a2); oA.w = siluf(a3);
        oB.x = siluf(b0); oB.y = siluf(b1); oB.z = siluf(b2); oB.w = siluf(b3);
        *(float4*)(Out + jA*64 + h0) = oA;
        *(float4*)(Out + jB*64 + h0) = oB;
    }
}

// ---------------- kernel 2: phase 1 (256 threads) ----------------
__global__ void __launch_bounds__(256) k_phase1(
    const float* __restrict__ w_embed,
    const float* __restrict__ r1_w0, const float* __restrict__ r1_b0,
    const float* __restrict__ r1_w1, const float* __restrict__ r1_b1,
    const float* __restrict__ r1_w2, const float* __restrict__ r1_b2,
    const float* __restrict__ r1_w3, const float* __restrict__ r1_b3,
    const float* __restrict__ mix_l0, const float* __restrict__ mix_l1,
    const float* __restrict__ mix_l2)
{
    extern __shared__ float sm[];
    float* Xin = sm;            // 512
    float* Ysm = Xin + 512;     // 512 (mask premultiplied)
    float* mk  = Ysm + 512;     // 64
    float* Ha  = mk + 64;       // 4096
    float* Hb  = Ha + 4096;     // 4096 (overlaid by G/S/msg/t2 after L3)
    float* Wb  = Hb + 4096;     // 4096  -> 13376 floats (53.5KB)
    float* G   = Hb;            // 576
    float* S   = Hb + 576;      // 16
    float* msg = Hb + 592;      // 1152
    float* t2  = Hb + 1744;     // 128

    int t = threadIdx.x;
    int node = blockIdx.x;
    int pbase = node * 64;

    for (int idx = t; idx < 512; idx += 256) Xin[idx] = g_rad[(size_t)pbase*8 + idx];
    for (int idx = t; idx < 512; idx += 256)
        Ysm[idx] = g_Y[(size_t)pbase*8 + idx] * g_mask[pbase + (idx >> 3)];
    if (t < 64) mk[t] = g_mask[pbase + t];
    for (int idx = t; idx < 512; idx += 256) Wb[idx] = r1_w0[idx];
    __syncthreads();

    dense_layer256<8>(Xin, 8, Wb, r1_b0, Ha, t);
    __syncthreads();
    for (int idx = t; idx < 4096; idx += 256) Wb[idx] = r1_w1[idx];
    __syncthreads();
    dense_layer256<64>(Ha, 64, Wb, r1_b1, Hb, t);
    __syncthreads();
    for (int idx = t; idx < 4096; idx += 256) Wb[idx] = r1_w2[idx];
    __syncthreads();
    dense_layer256<64>(Hb, 64, Wb, r1_b2, Ha, t);   // final H in Ha; Hb now free
    __syncthreads();

    // G[m][c] = sum_j maskY_m(j) * H[j][c]  (G overlays Hb)
    for (int idx = t; idx < 576; idx += 256) {
        int m = idx >> 6, c = idx & 63;
        float acc = 0.0f;
        #pragma unroll 8
        for (int j = 0; j < 64; ++j) {
            float yv = (m == 0) ? mk[j] : Ysm[j*8 + m - 1];
            acc += yv * Ha[j*64 + c];
        }
        G[idx] = acc;
    }
    if (t < 9) {
        float acc = 0.0f;
        for (int j = 0; j < 64; ++j) acc += (t == 0) ? mk[j] : Ysm[j*8 + t - 1];
        S[t] = acc;
    }
    __syncthreads();

    // msg: thread-half 0 does m=0..3 (w0+w1 streams); half 1 does m=4..8 (w2 stream)
    {
        int g = t >> 7;
        int k = t & 127;
        float wk = w_embed[k] * 0.0625f;
        const float* w3p = r1_w3 + k;
        if (g == 0) {
            float a0v = r1_b3[k] * S[0];
            float b3_1 = r1_b3[128 + k];
            float a1v = b3_1*S[1], a2v = b3_1*S[2], a3v = b3_1*S[3];
            #pragma unroll 4
            for (int c = 0; c < 64; ++c) {
                float w0 = __ldg(w3p + c*384);
                float w1 = __ldg(w3p + c*384 + 128);
                a0v += G[c]       * w0;
                a1v += G[64 + c]  * w1;
                a2v += G[128 + c] * w1;
                a3v += G[192 + c] * w1;
            }
            msg[k]         = a0v * wk;
            msg[128 + k]   = a1v * wk;
            msg[256 + k]   = a2v * wk;
            msg[384 + k]   = a3v * wk;
        } else {
            float b3_2 = r1_b3[256 + k];
            float a4v = b3_2*S[4], a5v = b3_2*S[5], a6v = b3_2*S[6],
                  a7v = b3_2*S[7], a8v = b3_2*S[8];
            #pragma unroll 4
            for (int c = 0; c < 64; ++c) {
                float w2 = __ldg(w3p + c*384 + 256);
                a4v += G[256 + c] * w2;
                a5v += G[320 + c] * w2;
                a6v += G[384 + c] * w2;
                a7v += G[448 + c] * w2;
                a8v += G[512 + c] * w2;
            }
            msg[4*128 + k] = a4v * wk;
            msg[5*128 + k] = a5v * wk;
            msg[6*128 + k] = a6v * wk;
            msg[7*128 + k] = a7v * wk;
            msg[8*128 + k] = a8v * wk;
        }
    }
    __syncthreads();
    if (t < 128) {
        float a4 = msg[4*128+t], a5 = msg[5*128+t], a6 = msg[6*128+t],
              a7 = msg[7*128+t], a8 = msg[8*128+t];
        t2[t] = a4*a4 + a5*a5 + a6*a6 + a7*a7 + a8*a8;
    }
    __syncthreads();

    // half 0: s1/h1 (l0+l2 streams); half 1: v1[0..2] (l1 stream)
    {
        int g = t >> 7;
        int k = t & 127;
        if (g == 0) {
            float s = 0.0f;
            const float* l0p = mix_l0 + k;
            const float* l2p = mix_l2 + k;
            #pragma unroll 4
            for (int c = 0; c < 128; ++c) {
                s += msg[c]*__ldg(l0p + c*128) + t2[c]*__ldg(l2p + c*128);
            }
            g_s1[node*128 + k] = s;
            g_h1[node*128 + k] = siluf(s);
        } else {
            float v0 = 0.0f, v1 = 0.0f, v2 = 0.0f;
            const float* l1p = mix_l1 + k;
            #pragma unroll 4
            for (int c = 0; c < 128; ++c) {
                float w1 = __ldg(l1p + c*128);
                v0 += msg[128 + c]*w1;
                v1 += msg[256 + c]*w1;
                v2 += msg[384 + c]*w1;
            }
            g_v1[(node*3 + 0)*128 + k] = v0;
            g_v1[(node*3 + 1)*128 + k] = v1;
            g_v1[(node*3 + 2)*128 + k] = v2;
        }
    }
}

// ---------------- kernel 3: phase 2 (256 threads) ----------------
__global__ void __launch_bounds__(256) k_phase2(
    const float* __restrict__ r2_w0, const float* __restrict__ r2_b0,
    const float* __restrict__ r2_w1, const float* __restrict__ r2_b1,
    const float* __restrict__ r2_w2, const float* __restrict__ r2_b2,
    const float* __restrict__ r2_w3, const float* __restrict__ r2_b3,
    const float* __restrict__ mix2)
{
    extern __shared__ float sm[];
    float* Xin  = sm;            // 512
    float* mk   = Xin + 512;     // 64
    float* Y1s  = mk + 64;       // 192
    float* Ha   = Y1s + 192;     // 4096
    float* Hb   = Ha + 4096;     // 4096
    float* Wb   = Hb + 4096;     // 4096
    float* prt  = Wb + 4096;     // 256
    float* msgS = prt + 256;     // 128  -> 13440 floats (53.8KB)

    int t = threadIdx.x;
    int node = blockIdx.x;
    int b = node >> 6;
    int pbase = node * 64;

    for (int idx = t; idx < 512; idx += 256) Xin[idx] = g_rad[(size_t)pbase*8 + idx];
    if (t < 64) mk[t] = g_mask[pbase + t];
    if (t < 192) {
        int j = t / 3, m = t - j*3;
        Y1s[t] = g_Y[(size_t)pbase*8 + j*8 + m] * g_mask[pbase + j];
    }
    for (int idx = t; idx < 512; idx += 256) Wb[idx] = r2_w0[idx];
    __syncthreads();

    dense_layer256<8>(Xin, 8, Wb, r2_b0, Ha, t);
    __syncthreads();
    for (int idx = t; idx < 4096; idx += 256) Wb[idx] = r2_w1[idx];
    __syncthreads();
    dense_layer256<64>(Ha, 64, Wb, r2_b1, Hb, t);
    __syncthreads();
    for (int idx = t; idx < 4096; idx += 256) Wb[idx] = r2_w2[idx];
    __syncthreads();
    dense_layer256<64>(Hb, 64, Wb, r2_b2, Ha, t);   // final H' in Ha
    __syncthreads();

    // half 0: acc_a (p = mask*h1); half 1: acc_b (q = Y1·v1). k = t&127.
    {
        int half = t >> 7;
        int k = t & 127;
        float P[64];
        float acc;
        if (half == 0) {
            float sp = 0.0f;
            #pragma unroll
            for (int j = 0; j < 64; ++j) {
                float p = mk[j] * __ldg(g_h1 + (b*64 + j)*128 + k);
                P[j] = p; sp += p;
            }
            acc = r2_b3[k] * sp;
            #pragma unroll 1
            for (int c = 0; c < 64; c += 4) {
                float w0 = __ldg(r2_w3 + (c+0)*256 + k);
                float w1 = __ldg(r2_w3 + (c+1)*256 + k);
                float w2 = __ldg(r2_w3 + (c+2)*256 + k);
                float w3 = __ldg(r2_w3 + (c+3)*256 + k);
                float s0 = 0.0f, s1 = 0.0f, s2 = 0.0f, s3 = 0.0f;
                #pragma unroll
                for (int j = 0; j < 64; ++j) {
                    float4 hv = *(const float4*)(Ha + j*64 + c);
                    float pj = P[j];
                    s0 += pj*hv.x; s1 += pj*hv.y; s2 += pj*hv.z; s3 += pj*hv.w;
                }
                acc += s0*w0 + s1*w1 + s2*w2 + s3*w3;
            }
        } else {
            float sq = 0.0f;
            #pragma unroll
            for (int j = 0; j < 64; ++j) {
                const float* vp = g_v1 + ((size_t)(b*64 + j)*3)*128 + k;
                float q = Y1s[j*3+0]*__ldg(vp) + Y1s[j*3+1]*__ldg(vp+128)
                        + Y1s[j*3+2]*__ldg(vp+256);
                P[j] = q; sq += q;
            }
            acc = r2_b3[128 + k] * sq;
            #pragma unroll 1
            for (int c = 0; c < 64; c += 4) {
                float w0 = __ldg(r2_w3 + (c+0)*256 + 128 + k);
                float w1 = __ldg(r2_w3 + (c+1)*256 + 128 + k);
                float w2 = __ldg(r2_w3 + (c+2)*256 + 128 + k);
                float w3 = __ldg(r2_w3 + (c+3)*256 + 128 + k);
                float s0 = 0.0f, s1 = 0.0f, s2 = 0.0f, s3 = 0.0f;
                #pragma unroll
                for (int j = 0; j < 64; ++j) {
                    float4 hv = *(const float4*)(Ha + j*64 + c);
                    float pj = P[j];
                    s0 += pj*hv.x; s1 += pj*hv.y; s2 += pj*hv.z; s3 += pj*hv.w;
                }
                acc += s0*w0 + s1*w1 + s2*w2 + s3*w3;
            }
        }
        prt[t] = acc;
    }
    __syncthreads();
    if (t < 128) msgS[t] = (prt[t] + prt[128 + t]) * 0.0625f;
    __syncthreads();
    if (t < 128) {
        float s2v = 0.0f;
        #pragma unroll 4
        for (int c = 0; c < 128; ++c) s2v += msgS[c] * __ldg(mix2 + c*128 + t);
        g_s2[node*128 + t] = s2v;
    }
}

// ---------------- kernel 4: final MLP (R10-exact: 8 nodes/block, 512 thr, FFMA2, unroll 8) ----------------
__global__ void __launch_bounds__(512) k_mlp(
    const float* __restrict__ tim,
    const float* __restrict__ w0, const float* __restrict__ b0,
    const float* __restrict__ w1, const float* __restrict__ b1,
    const float* __restrict__ w2, const float* __restrict__ b2,
    float* __restrict__ out)
{
    extern __shared__ float sm[];
    float* xs_t  = sm;              // [641][8] = 5128
    float* h0s_t = xs_t + 5128;     // [512][8] = 4096  -> 9224 floats (36.9KB)
    float* h1s_t = xs_t;            // overlays xs_t after layer0

    int t = threadIdx.x;
    int rbase = blockIdx.x * 8;

    for (int idx = t; idx < 8*641; idx += 512) {
        int c = idx >> 3, r = idx & 7;
        int node = rbase + r;
        float v;
        if (c < 128)       v = g_s1[node*128 + c];
        else if (c < 512)  v = g_v1[(size_t)node*384 + (c - 128)];
        else if (c < 640)  v = g_s2[node*128 + (c - 512)];
        else               v = tim[node >> 6];
        xs_t[c*8 + r] = v;
    }
    __syncthreads();

    {
        u64 acc[4];
        u64 bb = pk2(b0[t], b0[t]);
        #pragma unroll
        for (int i = 0; i < 4; ++i) acc[i] = bb;
        #pragma unroll 8
        for (int c = 0; c < 641; ++c) {
            float w = __ldg(w0 + c*512 + t);
            u64 wp = pk2(w, w);
            const longlong2* xp = (const longlong2*)(xs_t + c*8);
            longlong2 qa = xp[0], qb = xp[1];
            fma2(acc[0], (u64)qa.x, wp); fma2(acc[1], (u64)qa.y, wp);
            fma2(acc[2], (u64)qb.x, wp); fma2(acc[3], (u64)qb.y, wp);
        }
        #pragma unroll
        for (int i = 0; i < 4; ++i) {
            float2 p = upk(acc[i]);
            h0s_t[t*8 + 2*i]     = fmaxf(p.x, 0.0f);
            h0s_t[t*8 + 2*i + 1] = fmaxf(p.y, 0.0f);
        }
    }
    __syncthreads();

    {
        u64 acc[4];
        u64 bb = pk2(b1[t], b1[t]);
        #pragma unroll
        for (int i = 0; i < 4; ++i) acc[i] = bb;
        #pragma unroll 8
        for (int c = 0; c < 512; ++c) {
            float w = __ldg(w1 + c*512 + t);
            u64 wp = pk2(w, w);
            const longlong2* xp = (const longlong2*)(h0s_t + c*8);
            longlong2 qa = xp[0], qb = xp[1];
            fma2(acc[0], (u64)qa.x, wp); fma2(acc[1], (u64)qa.y, wp);
            fma2(acc[2], (u64)qb.x, wp); fma2(acc[3], (u64)qb.y, wp);
        }
        #pragma unroll
        for (int i = 0; i < 4; ++i) {
            float2 p = upk(acc[i]);
            h1s_t[t*8 + 2*i]     = fmaxf(p.x, 0.0f);
            h1s_t[t*8 + 2*i + 1] = fmaxf(p.y, 0.0f);
        }
    }
    __syncthreads();

    {
        int wid = t >> 5, lane = t & 31;
        if (wid < 8) {
            int r = wid;
            float p0 = 0.0f, p1 = 0.0f, p2 = 0.0f;
            for (int c = lane; c < 512; c += 32) {
                float hv = h1s_t[c*8 + r];
                p0 += hv * w2[c*3 + 0];
                p1 += hv * w2[c*3 + 1];
                p2 += hv * w2[c*3 + 2];
            }
            #pragma unroll
            for (int off = 16; off > 0; off >>= 1) {
                p0 += __shfl_down_sync(0xffffffffu, p0, off);
                p1 += __shfl_down_sync(0xffffffffu, p1, off);
                p2 += __shfl_down_sync(0xffffffffu, p2, off);
            }
            if (lane == 0) {
                int node = rbase + r;
                out[node*3 + 0] = p0 + b2[0];
                out[node*3 + 1] = p1 + b2[1];
                out[node*3 + 2] = p2 + b2[2];
            }
        }
    }
}

// ---------------- launch ----------------
extern "C" void kernel_launch(void* const* d_in, const int* in_sizes, int n_in,
                              void* d_out, int out_size)
{
    const float* frac    = (const float*)d_in[0];
    const float* tim     = (const float*)d_in[1];
    const float* cell    = (const float*)d_in[2];
    const float* w_embed = (const float*)d_in[3];
    const float* r1_w0 = (const float*)d_in[4];
    const float* r1_b0 = (const float*)d_in[5];
    const float* r1_w1 = (const float*)d_in[6];
    const float* r1_b1 = (const float*)d_in[7];
    const float* r1_w2 = (const float*)d_in[8];
    const float* r1_b2 = (const float*)d_in[9];
    const float* r1_w3 = (const float*)d_in[10];
    const float* r1_b3 = (const float*)d_in[11];
    const float* mix1_l0 = (const float*)d_in[12];
    const float* mix1_l1 = (const float*)d_in[13];
    const float* mix1_l2 = (const float*)d_in[14];
    const float* r2_w0 = (const float*)d_in[15];
    const float* r2_b0 = (const float*)d_in[16];
    const float* r2_w1 = (const float*)d_in[17];
    const float* r2_b1 = (const float*)d_in[18];
    const float* r2_w2 = (const float*)d_in[19];
    const float* r2_b2 = (const float*)d_in[20];
    const float* r2_w3 = (const float*)d_in[21];
    const float* r2_b3 = (const float*)d_in[22];
    const float* mix2  = (const float*)d_in[23];
    const float* mlp_w0 = (const float*)d_in[24];
    const float* mlp_b0 = (const float*)d_in[25];
    const float* mlp_w1 = (const float*)d_in[26];
    const float* mlp_b1 = (const float*)d_in[27];
    const float* mlp_w2 = (const float*)d_in[28];
    const float* mlp_b2 = (const float*)d_in[29];

    const int SM_P1  = 13376 * 4;
    const int SM_P2  = 13440 * 4;
    const int SM_MLP = (5128 + 4096) * 4;

    cudaFuncSetAttribute(k_phase1, cudaFuncAttributeMaxDynamicSharedMemorySize, SM_P1);
    cudaFuncSetAttribute(k_phase2, cudaFuncAttributeMaxDynamicSharedMemorySize, SM_P2);
    cudaFuncSetAttribute(k_mlp,    cudaFuncAttributeMaxDynamicSharedMemorySize, SM_MLP);
    cudaFuncSetAttribute(k_phase1, cudaFuncAttributePreferredSharedMemoryCarveout, 100);
    cudaFuncSetAttribute(k_phase2, cudaFuncAttributePreferredSharedMemoryCarveout, 100);
    cudaFuncSetAttribute(k_mlp,    cudaFuncAttributePreferredSharedMemoryCarveout, 100);

    k_geom<<<NPAIR/256, 256>>>(frac, cell);
    k_phase1<<<NNODE, 256, SM_P1>>>(w_embed,
        r1_w0, r1_b0, r1_w1, r1_b1, r1_w2, r1_b2, r1_w3, r1_b3,
        mix1_l0, mix1_l1, mix1_l2);
    k_phase2<<<NNODE, 256, SM_P2>>>(
        r2_w0, r2_b0, r2_w1, r2_b1, r2_w2, r2_b2, r2_w3, r2_b3, mix2);
    k_mlp<<<NNODE/8, 512, SM_MLP>>>(tim, mlp_w0, mlp_b0, mlp_w1, mlp_b1,
        mlp_w2, mlp_b2, (float*)d_out);
}

// round 16
// speedup vs baseline: 1.3243x; 1.3243x over previous
#include <cuda_runtime.h>
#include <math.h>

#define BB 32
#define NN 64
#define KK 128
#define NPAIR (BB*NN*NN)
#define NNODE (BB*NN)

__device__ float g_rad[NPAIR*8];
__device__ float g_Y[NPAIR*8];
__device__ float g_mask[NPAIR];
__device__ float g_h1[NNODE*KK];
__device__ float g_s1[NNODE*KK];
__device__ float g_v1[NNODE*3*KK];
__device__ float g_s2[NNODE*KK];

__device__ __forceinline__ float siluf(float x) { return x / (1.0f + __expf(-x)); }

typedef unsigned long long u64;
__device__ __forceinline__ u64 pk2(float lo, float hi) {
    u64 r; asm("mov.b64 %0, {%1,%2};" : "=l"(r) : "f"(lo), "f"(hi)); return r;
}
__device__ __forceinline__ void fma2(u64& a, u64 x, u64 y) {
    asm("fma.rn.f32x2 %0, %1, %2, %3;" : "=l"(a) : "l"(x), "l"(y), "l"(a));
}
__device__ __forceinline__ float2 upk(u64 v) {
    float2 o; asm("mov.b64 {%0,%1}, %2;" : "=f"(o.x), "=f"(o.y) : "l"(v)); return o;
}

// ---------------- kernel 1: pairwise geometry ----------------
__global__ void k_geom(const float* __restrict__ frac, const float* __restrict__ cell)
{
    int idx = blockIdx.x * blockDim.x + threadIdx.x;
    if (idx >= NPAIR) return;
    int b = idx >> 12;
    int i = (idx >> 6) & 63;
    int j = idx & 63;
    const float* fi = frac + (b*NN + i)*3;
    const float* fj = frac + (b*NN + j)*3;
    float d0 = fi[0]-fj[0], d1 = fi[1]-fj[1], d2 = fi[2]-fj[2];
    d0 -= rintf(d0); d1 -= rintf(d1); d2 -= rintf(d2);
    const float* C = cell + b*9;
    float x = d0*C[0] + d1*C[3] + d2*C[6];
    float y = d0*C[1] + d1*C[4] + d2*C[7];
    float z = d0*C[2] + d1*C[5] + d2*C[8];
    float r2 = fmaxf(x*x + y*y + z*z, 1e-12f);
    float r = sqrtf(r2);
    bool m = (r < 5.0f) && (i != j);
    float mf = m ? 1.0f : 0.0f;
    float rs = m ? r : 1.0f;
    float inv = 1.0f / rs;
    float ux = x*inv*mf, uy = y*inv*mf, uz = z*inv*mf;
    float u = rs * 0.2f;
    float u2 = u*u, u4 = u2*u2, u5 = u4*u;
    float fc = 1.0f - 21.0f*u5 + 35.0f*u5*u - 15.0f*u5*u2;
    fc = (u < 1.0f) ? fc : 0.0f;
    float pref = 0.6324555320336759f * inv * fc * mf;
    float w = 0.6283185307179586f * rs;
    float* rp = g_rad + (size_t)idx*8;
    #pragma unroll
    for (int n = 1; n <= 8; ++n) rp[n-1] = pref * sinf((float)n * w);
    const float s3 = 1.7320508075688772f, s5 = 2.23606797749979f, s15 = 3.872983346207417f;
    float* Y = g_Y + (size_t)idx*8;
    Y[0] = s3*ux; Y[1] = s3*uy; Y[2] = s3*uz;
    Y[3] = s15*ux*uy;
    Y[4] = s15*uy*uz;
    Y[5] = 0.5f*s5*(3.0f*uz*uz - 1.0f);
    Y[6] = s15*ux*uz;
    Y[7] = 0.5f*s15*(ux*ux - uy*uy);
    g_mask[idx] = mf;
}

// ---------------- 64-wide dense layer (silu), 2j x 4c, weights direct from gmem/L2 ----------------
// In: [64][ldi] smem (ldi mult of 4), Wg: [CDIM][64] GMEM, Out: [64][64] smem.
template<int CDIM>
__device__ __forceinline__ void dense_layer(const float* __restrict__ In, int ldi,
                                            const float* __restrict__ Wg,
                                            const float* __restrict__ bias,
                                            float* __restrict__ Out, int t)
{
    int jbase = t >> 4;
    int h0 = (t & 15) * 4;
    #pragma unroll 1
    for (int it = 0; it < 4; ++it) {
        int jA = jbase + 8*it;
        int jB = jA + 32;
        float a0 = bias[h0+0], a1 = bias[h0+1], a2 = bias[h0+2], a3 = bias[h0+3];
        float b0 = a0, b1 = a1, b2 = a2, b3 = a3;
        const float* inA = In + jA*ldi;
        const float* inB = In + jB*ldi;
        #pragma unroll 2
        for (int c = 0; c < CDIM; c += 4) {
            float4 av4 = *(const float4*)(inA + c);
            float4 bv4 = *(const float4*)(inB + c);
            float4 wv0 = __ldg((const float4*)(Wg + (c+0)*64 + h0));
            float4 wv1 = __ldg((const float4*)(Wg + (c+1)*64 + h0));
            float4 wv2 = __ldg((const float4*)(Wg + (c+2)*64 + h0));
            float4 wv3 = __ldg((const float4*)(Wg + (c+3)*64 + h0));
            a0 += av4.x*wv0.x; a1 += av4.x*wv0.y; a2 += av4.x*wv0.z; a3 += av4.x*wv0.w;
            b0 += bv4.x*wv0.x; b1 += bv4.x*wv0.y; b2 += bv4.x*wv0.z; b3 += bv4.x*wv0.w;
            a0 += av4.y*wv1.x; a1 += av4.y*wv1.y; a2 += av4.y*wv1.z; a3 += av4.y*wv1.w;
            b0 += bv4.y*wv1.x; b1 += bv4.y*wv1.y; b2 += bv4.y*wv1.z; b3 += bv4.y*wv1.w;
            a0 += av4.z*wv2.x; a1 += av4.z*wv2.y; a2 += av4.z*wv2.z; a3 += av4.z*wv2.w;
            b0 += bv4.z*wv2.x; b1 += bv4.z*wv2.y; b2 += bv4.z*wv2.z; b3 += bv4.z*wv2.w;
            a0 += av4.w*wv3.x; a1 += av4.w*wv3.y; a2 += av4.w*wv3.z; a3 += av4.w*wv3.w;
            b0 += bv4.w*wv3.x; b1 += bv4.w*wv3.y; b2 += bv4.w*wv3.z; b3 += bv4.w*wv3.w;
        }
        float4 oA, oB;
        oA.x = siluf(a0); oA.y = siluf(a1); oA.z = siluf(a2); oA.w = siluf(a3);
        oB.x = siluf(b0); oB.y = siluf(b1); oB.z = siluf(b2); oB.w = siluf(b3);
        *(float4*)(Out + jA*64 + h0) = oA;
        *(float4*)(Out + jB*64 + h0) = oB;
    }
}

// ---------------- kernel 2: phase 1 (128 threads, no Wb -> 37KB smem) ----------------
__global__ void __launch_bounds__(128, 6) k_phase1(
    const float* __restrict__ w_embed,
    const float* __restrict__ r1_w0, const float* __restrict__ r1_b0,
    const float* __restrict__ r1_w1, const float* __restrict__ r1_b1,
    const float* __restrict__ r1_w2, const float* __restrict__ r1_b2,
    const float* __restrict__ r1_w3, const float* __restrict__ r1_b3,
    const float* __restrict__ mix_l0, const float* __restrict__ mix_l1,
    const float* __restrict__ mix_l2)
{
    extern __shared__ float sm[];
    float* Xin = sm;            // 512
    float* Ysm = Xin + 512;     // 512 (mask premultiplied)
    float* mk  = Ysm + 512;     // 64
    float* Ha  = mk + 64;       // 4096
    float* Hb  = Ha + 4096;     // 4096 (overlaid by G/S/msg/t2 after L3)
    //                          -> 9280 floats (37.1KB)
    float* G   = Hb;            // 576
    float* S   = Hb + 576;      // 16
    float* msg = Hb + 592;      // 1152
    float* t2  = Hb + 1744;     // 128

    int t = threadIdx.x;
    int node = blockIdx.x;
    int pbase = node * 64;

    for (int idx = t; idx < 512; idx += 128) Xin[idx] = g_rad[(size_t)pbase*8 + idx];
    for (int idx = t; idx < 512; idx += 128)
        Ysm[idx] = g_Y[(size_t)pbase*8 + idx] * g_mask[pbase + (idx >> 3)];
    if (t < 64) mk[t] = g_mask[pbase + t];
    __syncthreads();

    dense_layer<8>(Xin, 8, r1_w0, r1_b0, Ha, t);
    __syncthreads();
    dense_layer<64>(Ha, 64, r1_w1, r1_b1, Hb, t);
    __syncthreads();
    dense_layer<64>(Hb, 64, r1_w2, r1_b2, Ha, t);   // final H in Ha; Hb now free
    __syncthreads();

    for (int idx = t; idx < 576; idx += 128) {
        int m = idx >> 6, c = idx & 63;
        float acc = 0.0f;
        #pragma unroll 8
        for (int j = 0; j < 64; ++j) {
            float yv = (m == 0) ? mk[j] : Ysm[j*8 + m - 1];
            acc += yv * Ha[j*64 + c];
        }
        G[idx] = acc;
    }
    if (t < 9) {
        float acc = 0.0f;
        for (int j = 0; j < 64; ++j) acc += (t == 0) ? mk[j] : Ysm[j*8 + t - 1];
        S[t] = acc;
    }
    __syncthreads();

    {
        int k = t;
        float wk = w_embed[k] * 0.0625f;
        float acc[9];
        float b3_0 = r1_b3[k], b3_1 = r1_b3[128 + k], b3_2 = r1_b3[256 + k];
        acc[0] = b3_0 * S[0];
        #pragma unroll
        for (int m = 1; m <= 3; ++m) acc[m] = b3_1 * S[m];
        #pragma unroll
        for (int m = 4; m <= 8; ++m) acc[m] = b3_2 * S[m];
        const float* w3p = r1_w3 + k;
        #pragma unroll 4
        for (int c = 0; c < 64; ++c) {
            float w0 = __ldg(w3p + c*384);
            float w1 = __ldg(w3p + c*384 + 128);
            float w2 = __ldg(w3p + c*384 + 256);
            acc[0] += G[c] * w0;
            acc[1] += G[64 + c]  * w1;
            acc[2] += G[128 + c] * w1;
            acc[3] += G[192 + c] * w1;
            acc[4] += G[256 + c] * w2;
            acc[5] += G[320 + c] * w2;
            acc[6] += G[384 + c] * w2;
            acc[7] += G[448 + c] * w2;
            acc[8] += G[512 + c] * w2;
        }
        #pragma unroll
        for (int m = 0; m < 9; ++m) msg[m*128 + k] = acc[m] * wk;
    }
    __syncthreads();
    {
        float a4 = msg[4*128+t], a5 = msg[5*128+t], a6 = msg[6*128+t],
              a7 = msg[7*128+t], a8 = msg[8*128+t];
        t2[t] = a4*a4 + a5*a5 + a6*a6 + a7*a7 + a8*a8;
    }
    __syncthreads();

    {
        int k = t;
        float s = 0.0f, v0 = 0.0f, v1 = 0.0f, v2 = 0.0f;
        const float* l0p = mix_l0 + k;
        const float* l1p = mix_l1 + k;
        const float* l2p = mix_l2 + k;
        #pragma unroll 4
        for (int c = 0; c < 128; ++c) {
            float w0 = __ldg(l0p + c*128);
            float w1 = __ldg(l1p + c*128);
            float w2 = __ldg(l2p + c*128);
            s  += msg[c]*w0 + t2[c]*w2;
            v0 += msg[128 + c]*w1;
            v1 += msg[256 + c]*w1;
            v2 += msg[384 + c]*w1;
        }
        g_s1[node*128 + k] = s;
        g_h1[node*128 + k] = siluf(s);
        g_v1[(node*3 + 0)*128 + k] = v0;
        g_v1[(node*3 + 1)*128 + k] = v1;
        g_v1[(node*3 + 2)*128 + k] = v2;
    }
}

// ---------------- kernel 3: phase 2 (128 threads, no Wb -> 36.4KB smem) ----------------
__global__ void __launch_bounds__(128, 6) k_phase2(
    const float* __restrict__ r2_w0, const float* __restrict__ r2_b0,
    const float* __restrict__ r2_w1, const float* __restrict__ r2_b1,
    const float* __restrict__ r2_w2, const float* __restrict__ r2_b2,
    const float* __restrict__ r2_w3, const float* __restrict__ r2_b3,
    const float* __restrict__ mix2)
{
    extern __shared__ float sm[];
    float* Xin  = sm;            // 512
    float* mk   = Xin + 512;     // 64
    float* Y1s  = mk + 64;       // 192
    float* Ha   = Y1s + 192;     // 4096
    float* Hb   = Ha + 4096;     // 4096
    float* msgS = Hb + 4096;     // 128  -> 9088 floats (36.4KB)

    int t = threadIdx.x;
    int node = blockIdx.x;
    int b = node >> 6;
    int pbase = node * 64;

    for (int idx = t; idx < 512; idx += 128) Xin[idx] = g_rad[(size_t)pbase*8 + idx];
    if (t < 64) mk[t] = g_mask[pbase + t];
    for (int idx = t; idx < 192; idx += 128) {
        int j = idx / 3, m = idx - j*3;
        Y1s[idx] = g_Y[(size_t)pbase*8 + j*8 + m] * g_mask[pbase + j];
    }
    __syncthreads();

    dense_layer<8>(Xin, 8, r2_w0, r2_b0, Ha, t);
    __syncthreads();
    dense_layer<64>(Ha, 64, r2_w1, r2_b1, Hb, t);
    __syncthreads();
    dense_layer<64>(Hb, 64, r2_w2, r2_b2, Ha, t);   // final H' in Ha
    __syncthreads();

    int k = t;
    float P[64];
    float acc_a, acc_b;
    {
        float sp = 0.0f;
        #pragma unroll
        for (int j = 0; j < 64; ++j) {
            float p = mk[j] * __ldg(g_h1 + (b*64 + j)*128 + k);
            P[j] = p; sp += p;
        }
        float acc = r2_b3[k] * sp;
        #pragma unroll 1
        for (int c = 0; c < 64; c += 4) {
            float w0 = __ldg(r2_w3 + (c+0)*256 + k);
            float w1 = __ldg(r2_w3 + (c+1)*256 + k);
            float w2 = __ldg(r2_w3 + (c+2)*256 + k);
            float w3 = __ldg(r2_w3 + (c+3)*256 + k);
            float s0 = 0.0f, s1 = 0.0f, s2 = 0.0f, s3 = 0.0f;
            #pragma unroll
            for (int j = 0; j < 64; ++j) {
                float4 hv = *(const float4*)(Ha + j*64 + c);
                float pj = P[j];
                s0 += pj*hv.x; s1 += pj*hv.y; s2 += pj*hv.z; s3 += pj*hv.w;
            }
            acc += s0*w0 + s1*w1 + s2*w2 + s3*w3;
        }
        acc_a = acc;
    }
    {
        float sq = 0.0f;
        #pragma unroll
        for (int j = 0; j < 64; ++j) {
            const float* vp = g_v1 + ((size_t)(b*64 + j)*3)*128 + k;
            float q = Y1s[j*3+0]*__ldg(vp) + Y1s[j*3+1]*__ldg(vp+128) + Y1s[j*3+2]*__ldg(vp+256);
            P[j] = q; sq += q;
        }
        float acc = r2_b3[128 + k] * sq;
        #pragma unroll 1
        for (int c = 0; c < 64; c += 4) {
            float w0 = __ldg(r2_w3 + (c+0)*256 + 128 + k);
            float w1 = __ldg(r2_w3 + (c+1)*256 + 128 + k);
            float w2 = __ldg(r2_w3 + (c+2)*256 + 128 + k);
            float w3 = __ldg(r2_w3 + (c+3)*256 + 128 + k);
            float s0 = 0.0f, s1 = 0.0f, s2 = 0.0f, s3 = 0.0f;
            #pragma unroll
            for (int j = 0; j < 64; ++j) {
                float4 hv = *(const float4*)(Ha + j*64 + c);
                float pj = P[j];
                s0 += pj*hv.x; s1 += pj*hv.y; s2 += pj*hv.z; s3 += pj*hv.w;
            }
            acc += s0*w0 + s1*w1 + s2*w2 + s3*w3;
        }
        acc_b = acc;
    }
    msgS[k] = (acc_a + acc_b) * 0.0625f;
    __syncthreads();
    {
        float s2v = 0.0f;
        #pragma unroll 4
        for (int c = 0; c < 128; ++c) s2v += msgS[c] * __ldg(mix2 + c*128 + k);
        g_s2[node*128 + k] = s2v;
    }
}

// ---------------- kernel 4: final MLP (R10-exact: 8 nodes/block, 512 thr, FFMA2, unroll 8) ----------------
__global__ void __launch_bounds__(512) k_mlp(
    const float* __restrict__ tim,
    const float* __restrict__ w0, const float* __restrict__ b0,
    const float* __restrict__ w1, const float* __restrict__ b1,
    const float* __restrict__ w2, const float* __restrict__ b2,
    float* __restrict__ out)
{
    extern __shared__ float sm[];
    float* xs_t  = sm;              // [641][8] = 5128
    float* h0s_t = xs_t + 5128;     // [512][8] = 4096  -> 9224 floats (36.9KB)
    float* h1s_t = xs_t;            // overlays xs_t after layer0

    int t = threadIdx.x;
    int rbase = blockIdx.x * 8;

    for (int idx = t; idx < 8*641; idx += 512) {
        int c = idx >> 3, r = idx & 7;
        int node = rbase + r;
        float v;
        if (c < 128)       v = g_s1[node*128 + c];
        else if (c < 512)  v = g_v1[(size_t)node*384 + (c - 128)];
        else if (c < 640)  v = g_s2[node*128 + (c - 512)];
        else               v = tim[node >> 6];
        xs_t[c*8 + r] = v;
    }
    __syncthreads();

    {
        u64 acc[4];
        u64 bb = pk2(b0[t], b0[t]);
        #pragma unroll
        for (int i = 0; i < 4; ++i) acc[i] = bb;
        #pragma unroll 8
        for (int c = 0; c < 641; ++c) {
            float w = __ldg(w0 + c*512 + t);
            u64 wp = pk2(w, w);
            const longlong2* xp = (const longlong2*)(xs_t + c*8);
            longlong2 qa = xp[0], qb = xp[1];
            fma2(acc[0], (u64)qa.x, wp); fma2(acc[1], (u64)qa.y, wp);
            fma2(acc[2], (u64)qb.x, wp); fma2(acc[3], (u64)qb.y, wp);
        }
        #pragma unroll
        for (int i = 0; i < 4; ++i) {
            float2 p = upk(acc[i]);
            h0s_t[t*8 + 2*i]     = fmaxf(p.x, 0.0f);
            h0s_t[t*8 + 2*i + 1] = fmaxf(p.y, 0.0f);
        }
    }
    __syncthreads();

    {
        u64 acc[4];
        u64 bb = pk2(b1[t], b1[t]);
        #pragma unroll
        for (int i = 0; i < 4; ++i) acc[i] = bb;
        #pragma unroll 8
        for (int c = 0; c < 512; ++c) {
            float w = __ldg(w1 + c*512 + t);
            u64 wp = pk2(w, w);
            const longlong2* xp = (const longlong2*)(h0s_t + c*8);
            longlong2 qa = xp[0], qb = xp[1];
            fma2(acc[0], (u64)qa.x, wp); fma2(acc[1], (u64)qa.y, wp);
            fma2(acc[2], (u64)qb.x, wp); fma2(acc[3], (u64)qb.y, wp);
        }
        #pragma unroll
        for (int i = 0; i < 4; ++i) {
            float2 p = upk(acc[i]);
            h1s_t[t*8 + 2*i]     = fmaxf(p.x, 0.0f);
            h1s_t[t*8 + 2*i + 1] = fmaxf(p.y, 0.0f);
        }
    }
    __syncthreads();

    {
        int wid = t >> 5, lane = t & 31;
        if (wid < 8) {
            int r = wid;
            float p0 = 0.0f, p1 = 0.0f, p2 = 0.0f;
            for (int c = lane; c < 512; c += 32) {
                float hv = h1s_t[c*8 + r];
                p0 += hv * w2[c*3 + 0];
                p1 += hv * w2[c*3 + 1];
                p2 += hv * w2[c*3 + 2];
            }
            #pragma unroll
            for (int off = 16; off > 0; off >>= 1) {
                p0 += __shfl_down_sync(0xffffffffu, p0, off);
                p1 += __shfl_down_sync(0xffffffffu, p1, off);
                p2 += __shfl_down_sync(0xffffffffu, p2, off);
            }
            if (lane == 0) {
                int node = rbase + r;
                out[node*3 + 0] = p0 + b2[0];
                out[node*3 + 1] = p1 + b2[1];
                out[node*3 + 2] = p2 + b2[2];
            }
        }
    }
}

// ---------------- launch ----------------
extern "C" void kernel_launch(void* const* d_in, const int* in_sizes, int n_in,
                              void* d_out, int out_size)
{
    const float* frac    = (const float*)d_in[0];
    const float* tim     = (const float*)d_in[1];
    const float* cell    = (const float*)d_in[2];
    const float* w_embed = (const float*)d_in[3];
    const float* r1_w0 = (const float*)d_in[4];
    const float* r1_b0 = (const float*)d_in[5];
    const float* r1_w1 = (const float*)d_in[6];
    const float* r1_b1 = (const float*)d_in[7];
    const float* r1_w2 = (const float*)d_in[8];
    const float* r1_b2 = (const float*)d_in[9];
    const float* r1_w3 = (const float*)d_in[10];
    const float* r1_b3 = (const float*)d_in[11];
    const float* mix1_l0 = (const float*)d_in[12];
    const float* mix1_l1 = (const float*)d_in[13];
    const float* mix1_l2 = (const float*)d_in[14];
    const float* r2_w0 = (const float*)d_in[15];
    const float* r2_b0 = (const float*)d_in[16];
    const float* r2_w1 = (const float*)d_in[17];
    const float* r2_b1 = (const float*)d_in[18];
    const float* r2_w2 = (const float*)d_in[19];
    const float* r2_b2 = (const float*)d_in[20];
    const float* r2_w3 = (const float*)d_in[21];
    const float* r2_b3 = (const float*)d_in[22];
    const float* mix2  = (const float*)d_in[23];
    const float* mlp_w0 = (const float*)d_in[24];
    const float* mlp_b0 = (const float*)d_in[25];
    const float* mlp_w1 = (const float*)d_in[26];
    const float* mlp_b1 = (const float*)d_in[27];
    const float* mlp_w2 = (const float*)d_in[28];
    const float* mlp_b2 = (const float*)d_in[29];

    const int SM_P1  = 9280 * 4;
    const int SM_P2  = 9088 * 4;
    const int SM_MLP = (5128 + 4096) * 4;

    cudaFuncSetAttribute(k_phase1, cudaFuncAttributeMaxDynamicSharedMemorySize, SM_P1);
    cudaFuncSetAttribute(k_phase2, cudaFuncAttributeMaxDynamicSharedMemorySize, SM_P2);
    cudaFuncSetAttribute(k_mlp,    cudaFuncAttributeMaxDynamicSharedMemorySize, SM_MLP);
    cudaFuncSetAttribute(k_phase1, cudaFuncAttributePreferredSharedMemoryCarveout, 100);
    cudaFuncSetAttribute(k_phase2, cudaFuncAttributePreferredSharedMemoryCarveout, 100);
    cudaFuncSetAttribute(k_mlp,    cudaFuncAttributePreferredSharedMemoryCarveout, 100);

    k_geom<<<NPAIR/256, 256>>>(frac, cell);
    k_phase1<<<NNODE, 128, SM_P1>>>(w_embed,
        r1_w0, r1_b0, r1_w1, r1_b1, r1_w2, r1_b2, r1_w3, r1_b3,
        mix1_l0, mix1_l1, mix1_l2);
    k_phase2<<<NNODE, 128, SM_P2>>>(
        r2_w0, r2_b0, r2_w1, r2_b1, r2_w2, r2_b2, r2_w3, r2_b3, mix2);
    k_mlp<<<NNODE/8, 512, SM_MLP>>>(tim, mlp_w0, mlp_b0, mlp_w1, mlp_b1,
        mlp_w2, mlp_b2, (float*)d_out);
}

// round 17
// speedup vs baseline: 1.4067x; 1.0622x over previous
#include <cuda_runtime.h>
#include <math.h>

#define BB 32
#define NN 64
#define KK 128
#define NPAIR (BB*NN*NN)
#define NNODE (BB*NN)

__device__ float g_rad[NPAIR*8];
__device__ float g_Y[NPAIR*8];
__device__ float g_mask[NPAIR];
__device__ float g_h1[NNODE*KK];
__device__ float g_s1[NNODE*KK];
__device__ float g_v1[NNODE*3*KK];
__device__ float g_s2[NNODE*KK];

__device__ __forceinline__ float siluf(float x) { return x / (1.0f + __expf(-x)); }

typedef unsigned long long u64;
__device__ __forceinline__ u64 pk2(float lo, float hi) {
    u64 r; asm("mov.b64 %0, {%1,%2};" : "=l"(r) : "f"(lo), "f"(hi)); return r;
}
__device__ __forceinline__ void fma2(u64& a, u64 x, u64 y) {
    asm("fma.rn.f32x2 %0, %1, %2, %3;" : "=l"(a) : "l"(x), "l"(y), "l"(a));
}
__device__ __forceinline__ float2 upk(u64 v) {
    float2 o; asm("mov.b64 {%0,%1}, %2;" : "=f"(o.x), "=f"(o.y) : "l"(v)); return o;
}

// ---------------- kernel 1: pairwise geometry ----------------
__global__ void k_geom(const float* __restrict__ frac, const float* __restrict__ cell)
{
    int idx = blockIdx.x * blockDim.x + threadIdx.x;
    if (idx >= NPAIR) return;
    int b = idx >> 12;
    int i = (idx >> 6) & 63;
    int j = idx & 63;
    const float* fi = frac + (b*NN + i)*3;
    const float* fj = frac + (b*NN + j)*3;
    float d0 = fi[0]-fj[0], d1 = fi[1]-fj[1], d2 = fi[2]-fj[2];
    d0 -= rintf(d0); d1 -= rintf(d1); d2 -= rintf(d2);
    const float* C = cell + b*9;
    float x = d0*C[0] + d1*C[3] + d2*C[6];
    float y = d0*C[1] + d1*C[4] + d2*C[7];
    float z = d0*C[2] + d1*C[5] + d2*C[8];
    float r2 = fmaxf(x*x + y*y + z*z, 1e-12f);
    float r = sqrtf(r2);
    bool m = (r < 5.0f) && (i != j);
    float mf = m ? 1.0f : 0.0f;
    float rs = m ? r : 1.0f;
    float inv = 1.0f / rs;
    float ux = x*inv*mf, uy = y*inv*mf, uz = z*inv*mf;
    float u = rs * 0.2f;
    float u2 = u*u, u4 = u2*u2, u5 = u4*u;
    float fc = 1.0f - 21.0f*u5 + 35.0f*u5*u - 15.0f*u5*u2;
    fc = (u < 1.0f) ? fc : 0.0f;
    float pref = 0.6324555320336759f * inv * fc * mf;
    float w = 0.6283185307179586f * rs;
    float* rp = g_rad + (size_t)idx*8;
    #pragma unroll
    for (int n = 1; n <= 8; ++n) rp[n-1] = pref * sinf((float)n * w);
    const float s3 = 1.7320508075688772f, s5 = 2.23606797749979f, s15 = 3.872983346207417f;
    float* Y = g_Y + (size_t)idx*8;
    Y[0] = s3*ux; Y[1] = s3*uy; Y[2] = s3*uz;
    Y[3] = s15*ux*uy;
    Y[4] = s15*uy*uz;
    Y[5] = 0.5f*s5*(3.0f*uz*uz - 1.0f);
    Y[6] = s15*ux*uz;
    Y[7] = 0.5f*s15*(ux*ux - uy*uy);
    g_mask[idx] = mf;
}

// ---------------- 64-wide dense layer (silu), 2j x 4c, weights direct from gmem/L2 ----------------
template<int CDIM>
__device__ __forceinline__ void dense_layer(const float* __restrict__ In, int ldi,
                                            const float* __restrict__ Wg,
                                            const float* __restrict__ bias,
                                            float* __restrict__ Out, int t)
{
    int jbase = t >> 4;
    int h0 = (t & 15) * 4;
    #pragma unroll 1
    for (int it = 0; it < 4; ++it) {
        int jA = jbase + 8*it;
        int jB = jA + 32;
        float a0 = bias[h0+0], a1 = bias[h0+1], a2 = bias[h0+2], a3 = bias[h0+3];
        float b0 = a0, b1 = a1, b2 = a2, b3 = a3;
        const float* inA = In + jA*ldi;
        const float* inB = In + jB*ldi;
        #pragma unroll 2
        for (int c = 0; c < CDIM; c += 4) {
            float4 av4 = *(const float4*)(inA + c);
            float4 bv4 = *(const float4*)(inB + c);
            float4 wv0 = __ldg((const float4*)(Wg + (c+0)*64 + h0));
            float4 wv1 = __ldg((const float4*)(Wg + (c+1)*64 + h0));
            float4 wv2 = __ldg((const float4*)(Wg + (c+2)*64 + h0));
            float4 wv3 = __ldg((const float4*)(Wg + (c+3)*64 + h0));
            a0 += av4.x*wv0.x; a1 += av4.x*wv0.y; a2 += av4.x*wv0.z; a3 += av4.x*wv0.w;
            b0 += bv4.x*wv0.x; b1 += bv4.x*wv0.y; b2 += bv4.x*wv0.z; b3 += bv4.x*wv0.w;
            a0 += av4.y*wv1.x; a1 += av4.y*wv1.y; a2 += av4.y*wv1.z; a3 += av4.y*wv1.w;
            b0 += bv4.y*wv1.x; b1 += bv4.y*wv1.y; b2 += bv4.y*wv1.z; b3 += bv4.y*wv1.w;
            a0 += av4.z*wv2.x; a1 += av4.z*wv2.y; a2 += av4.z*wv2.z; a3 += av4.z*wv2.w;
            b0 += bv4.z*wv2.x; b1 += bv4.z*wv2.y; b2 += bv4.z*wv2.z; b3 += bv4.z*wv2.w;
            a0 += av4.w*wv3.x; a1 += av4.w*wv3.y; a2 += av4.w*wv3.z; a3 += av4.w*wv3.w;
            b0 += bv4.w*wv3.x; b1 += bv4.w*wv3.y; b2 += bv4.w*wv3.z; b3 += bv4.w*wv3.w;
        }
        float4 oA, oB;
        oA.x = siluf(a0); oA.y = siluf(a1); oA.z = siluf(a2); oA.w = siluf(a3);
        oB.x = siluf(b0); oB.y = siluf(b1); oB.z = siluf(b2); oB.w = siluf(b3);
        *(float4*)(Out + jA*64 + h0) = oA;
        *(float4*)(Out + jB*64 + h0) = oB;
    }
}

// ---------------- kernel 2: phase 1 (128 threads, 37KB smem) ----------------
__global__ void __launch_bounds__(128, 6) k_phase1(
    const float* __restrict__ w_embed,
    const float* __restrict__ r1_w0, const float* __restrict__ r1_b0,
    const float* __restrict__ r1_w1, const float* __restrict__ r1_b1,
    const float* __restrict__ r1_w2, const float* __restrict__ r1_b2,
    const float* __restrict__ r1_w3, const float* __restrict__ r1_b3,
    const float* __restrict__ mix_l0, const float* __restrict__ mix_l1,
    const float* __restrict__ mix_l2)
{
    extern __shared__ float sm[];
    float* Xin = sm;            // 512
    float* Ysm = Xin + 512;     // 512 (mask premultiplied)
    float* mk  = Ysm + 512;     // 64
    float* Ha  = mk + 64;       // 4096
    float* Hb  = Ha + 4096;     // 4096  -> 9280 floats (37.1KB)
    float* G   = Hb;            // 576
    float* S   = Hb + 576;      // 16
    float* msg = Hb + 592;      // 1152
    float* t2  = Hb + 1744;     // 128

    int t = threadIdx.x;
    int node = blockIdx.x;
    int pbase = node * 64;

    for (int idx = t; idx < 512; idx += 128) Xin[idx] = g_rad[(size_t)pbase*8 + idx];
    for (int idx = t; idx < 512; idx += 128)
        Ysm[idx] = g_Y[(size_t)pbase*8 + idx] * g_mask[pbase + (idx >> 3)];
    if (t < 64) mk[t] = g_mask[pbase + t];
    __syncthreads();

    dense_layer<8>(Xin, 8, r1_w0, r1_b0, Ha, t);
    __syncthreads();
    dense_layer<64>(Ha, 64, r1_w1, r1_b1, Hb, t);
    __syncthreads();
    dense_layer<64>(Hb, 64, r1_w2, r1_b2, Ha, t);   // final H in Ha; Hb now free
    __syncthreads();

    for (int idx = t; idx < 576; idx += 128) {
        int m = idx >> 6, c = idx & 63;
        float acc = 0.0f;
        #pragma unroll 8
        for (int j = 0; j < 64; ++j) {
            float yv = (m == 0) ? mk[j] : Ysm[j*8 + m - 1];
            acc += yv * Ha[j*64 + c];
        }
        G[idx] = acc;
    }
    if (t < 9) {
        float acc = 0.0f;
        for (int j = 0; j < 64; ++j) acc += (t == 0) ? mk[j] : Ysm[j*8 + t - 1];
        S[t] = acc;
    }
    __syncthreads();

    {
        int k = t;
        float wk = w_embed[k] * 0.0625f;
        float acc[9];
        float b3_0 = r1_b3[k], b3_1 = r1_b3[128 + k], b3_2 = r1_b3[256 + k];
        acc[0] = b3_0 * S[0];
        #pragma unroll
        for (int m = 1; m <= 3; ++m) acc[m] = b3_1 * S[m];
        #pragma unroll
        for (int m = 4; m <= 8; ++m) acc[m] = b3_2 * S[m];
        const float* w3p = r1_w3 + k;
        #pragma unroll 8
        for (int c = 0; c < 64; ++c) {
            float w0 = __ldg(w3p + c*384);
            float w1 = __ldg(w3p + c*384 + 128);
            float w2 = __ldg(w3p + c*384 + 256);
            acc[0] += G[c] * w0;
            acc[1] += G[64 + c]  * w1;
            acc[2] += G[128 + c] * w1;
            acc[3] += G[192 + c] * w1;
            acc[4] += G[256 + c] * w2;
            acc[5] += G[320 + c] * w2;
            acc[6] += G[384 + c] * w2;
            acc[7] += G[448 + c] * w2;
            acc[8] += G[512 + c] * w2;
        }
        #pragma unroll
        for (int m = 0; m < 9; ++m) msg[m*128 + k] = acc[m] * wk;
    }
    __syncthreads();
    {
        float a4 = msg[4*128+t], a5 = msg[5*128+t], a6 = msg[6*128+t],
              a7 = msg[7*128+t], a8 = msg[8*128+t];
        t2[t] = a4*a4 + a5*a5 + a6*a6 + a7*a7 + a8*a8;
    }
    __syncthreads();

    {
        int k = t;
        float s = 0.0f, v0 = 0.0f, v1 = 0.0f, v2 = 0.0f;
        const float* l0p = mix_l0 + k;
        const float* l1p = mix_l1 + k;
        const float* l2p = mix_l2 + k;
        #pragma unroll 8
        for (int c = 0; c < 128; ++c) {
            float w0 = __ldg(l0p + c*128);
            float w1 = __ldg(l1p + c*128);
            float w2 = __ldg(l2p + c*128);
            s  += msg[c]*w0 + t2[c]*w2;
            v0 += msg[128 + c]*w1;
            v1 += msg[256 + c]*w1;
            v2 += msg[384 + c]*w1;
        }
        g_s1[node*128 + k] = s;
        g_h1[node*128 + k] = siluf(s);
        g_v1[(node*3 + 0)*128 + k] = v0;
        g_v1[(node*3 + 1)*128 + k] = v1;
        g_v1[(node*3 + 2)*128 + k] = v2;
    }
}

// ---------------- kernel 3: phase 2 (128 threads, no reg cap -> no spills) ----------------
__global__ void __launch_bounds__(128) k_phase2(
    const float* __restrict__ r2_w0, const float* __restrict__ r2_b0,
    const float* __restrict__ r2_w1, const float* __restrict__ r2_b1,
    const float* __restrict__ r2_w2, const float* __restrict__ r2_b2,
    const float* __restrict__ r2_w3, const float* __restrict__ r2_b3,
    const float* __restrict__ mix2)
{
    extern __shared__ float sm[];
    float* Xin  = sm;            // 512
    float* mk   = Xin + 512;     // 64
    float* Y1s  = mk + 64;       // 192
    float* Ha   = Y1s + 192;     // 4096
    float* Hb   = Ha + 4096;     // 4096
    float* msgS = Hb + 4096;     // 128  -> 9088 floats (36.4KB)

    int t = threadIdx.x;
    int node = blockIdx.x;
    int b = node >> 6;
    int pbase = node * 64;

    for (int idx = t; idx < 512; idx += 128) Xin[idx] = g_rad[(size_t)pbase*8 + idx];
    if (t < 64) mk[t] = g_mask[pbase + t];
    for (int idx = t; idx < 192; idx += 128) {
        int j = idx / 3, m = idx - j*3;
        Y1s[idx] = g_Y[(size_t)pbase*8 + j*8 + m] * g_mask[pbase + j];
    }
    __syncthreads();

    dense_layer<8>(Xin, 8, r2_w0, r2_b0, Ha, t);
    __syncthreads();
    dense_layer<64>(Ha, 64, r2_w1, r2_b1, Hb, t);
    __syncthreads();
    dense_layer<64>(Hb, 64, r2_w2, r2_b2, Ha, t);   // final H' in Ha
    __syncthreads();

    int k = t;
    float P[64];
    float acc_a, acc_b;
    {
        float sp = 0.0f;
        #pragma unroll
        for (int j = 0; j < 64; ++j) {
            float p = mk[j] * __ldg(g_h1 + (b*64 + j)*128 + k);
            P[j] = p; sp += p;
        }
        float acc = r2_b3[k] * sp;
        #pragma unroll 1
        for (int c = 0; c < 64; c += 4) {
            float w0 = __ldg(r2_w3 + (c+0)*256 + k);
            float w1 = __ldg(r2_w3 + (c+1)*256 + k);
            float w2 = __ldg(r2_w3 + (c+2)*256 + k);
            float w3 = __ldg(r2_w3 + (c+3)*256 + k);
            float s0 = 0.0f, s1 = 0.0f, s2 = 0.0f, s3 = 0.0f;
            float s0b = 0.0f, s1b = 0.0f, s2b = 0.0f, s3b = 0.0f;
            #pragma unroll
            for (int j = 0; j < 64; j += 2) {
                float4 hv  = *(const float4*)(Ha + j*64 + c);
                float4 hv2 = *(const float4*)(Ha + (j+1)*64 + c);
                float pj  = P[j];
                float pj2 = P[j+1];
                s0  += pj*hv.x;   s1  += pj*hv.y;   s2  += pj*hv.z;   s3  += pj*hv.w;
                s0b += pj2*hv2.x; s1b += pj2*hv2.y; s2b += pj2*hv2.z; s3b += pj2*hv2.w;
            }
            acc += (s0+s0b)*w0 + (s1+s1b)*w1 + (s2+s2b)*w2 + (s3+s3b)*w3;
        }
        acc_a = acc;
    }
    {
        float sq = 0.0f;
        #pragma unroll
        for (int j = 0; j < 64; ++j) {
            const float* vp = g_v1 + ((size_t)(b*64 + j)*3)*128 + k;
            float q = Y1s[j*3+0]*__ldg(vp) + Y1s[j*3+1]*__ldg(vp+128) + Y1s[j*3+2]*__ldg(vp+256);
            P[j] = q; sq += q;
        }
        float acc = r2_b3[128 + k] * sq;
        #pragma unroll 1
        for (int c = 0; c < 64; c += 4) {
            float w0 = __ldg(r2_w3 + (c+0)*256 + 128 + k);
            float w1 = __ldg(r2_w3 + (c+1)*256 + 128 + k);
            float w2 = __ldg(r2_w3 + (c+2)*256 + 128 + k);
            float w3 = __ldg(r2_w3 + (c+3)*256 + 128 + k);
            float s0 = 0.0f, s1 = 0.0f, s2 = 0.0f, s3 = 0.0f;
            float s0b = 0.0f, s1b = 0.0f, s2b = 0.0f, s3b = 0.0f;
            #pragma unroll
            for (int j = 0; j < 64; j += 2) {
                float4 hv  = *(const float4*)(Ha + j*64 + c);
                float4 hv2 = *(const float4*)(Ha + (j+1)*64 + c);
                float pj  = P[j];
                float pj2 = P[j+1];
                s0  += pj*hv.x;   s1  += pj*hv.y;   s2  += pj*hv.z;   s3  += pj*hv.w;
                s0b += pj2*hv2.x; s1b += pj2*hv2.y; s2b += pj2*hv2.z; s3b += pj2*hv2.w;
            }
            acc += (s0+s0b)*w0 + (s1+s1b)*w1 + (s2+s2b)*w2 + (s3+s3b)*w3;
        }
        acc_b = acc;
    }
    msgS[k] = (acc_a + acc_b) * 0.0625f;
    __syncthreads();
    {
        float s2v = 0.0f;
        #pragma unroll 8
        for (int c = 0; c < 128; ++c) s2v += msgS[c] * __ldg(mix2 + c*128 + k);
        g_s2[node*128 + k] = s2v;
    }
}

// ---------------- kernel 4: final MLP (8 nodes/block, 512 thr, FFMA2, 8 acc chains) ----------------
__global__ void __launch_bounds__(512) k_mlp(
    const float* __restrict__ tim,
    const float* __restrict__ w0, const float* __restrict__ b0,
    const float* __restrict__ w1, const float* __restrict__ b1,
    const float* __restrict__ w2, const float* __restrict__ b2,
    float* __restrict__ out)
{
    extern __shared__ float sm[];
    float* xs_t  = sm;              // [641][8] = 5128
    float* h0s_t = xs_t + 5128;     // [512][8] = 4096  -> 9224 floats (36.9KB)
    float* h1s_t = xs_t;            // overlays xs_t after layer0

    int t = threadIdx.x;
    int rbase = blockIdx.x * 8;

    for (int idx = t; idx < 8*641; idx += 512) {
        int c = idx >> 3, r = idx & 7;
        int node = rbase + r;
        float v;
        if (c < 128)       v = g_s1[node*128 + c];
        else if (c < 512)  v = g_v1[(size_t)node*384 + (c - 128)];
        else if (c < 640)  v = g_s2[node*128 + (c - 512)];
        else               v = tim[node >> 6];
        xs_t[c*8 + r] = v;
    }
    __syncthreads();

    // layer 0: 641 -> 512, relu. 8 independent FFMA2 chains (even/odd c).
    {
        u64 accA[4], accB[4];
        u64 bb = pk2(b0[t], b0[t]);
        u64 zz = pk2(0.0f, 0.0f);
        #pragma unroll
        for (int i = 0; i < 4; ++i) { accA[i] = bb; accB[i] = zz; }
        #pragma unroll 4
        for (int c = 0; c < 640; c += 2) {
            float wE = __ldg(w0 + (c+0)*512 + t);
            float wO = __ldg(w0 + (c+1)*512 + t);
            u64 wpE = pk2(wE, wE);
            u64 wpO = pk2(wO, wO);
            const longlong2* xpE = (const longlong2*)(xs_t + (c+0)*8);
            const longlong2* xpO = (const longlong2*)(xs_t + (c+1)*8);
            longlong2 qaE = xpE[0], qbE = xpE[1];
            longlong2 qaO = xpO[0], qbO = xpO[1];
            fma2(accA[0], (u64)qaE.x, wpE); fma2(accA[1], (u64)qaE.y, wpE);
            fma2(accA[2], (u64)qbE.x, wpE); fma2(accA[3], (u64)qbE.y, wpE);
            fma2(accB[0], (u64)qaO.x, wpO); fma2(accB[1], (u64)qaO.y, wpO);
            fma2(accB[2], (u64)qbO.x, wpO); fma2(accB[3], (u64)qbO.y, wpO);
        }
        // last column c = 640
        {
            float w = __ldg(w0 + 640*512 + t);
            u64 wp = pk2(w, w);
            const longlong2* xp = (const longlong2*)(xs_t + 640*8);
            longlong2 qa = xp[0], qb = xp[1];
            fma2(accA[0], (u64)qa.x, wp); fma2(accA[1], (u64)qa.y, wp);
            fma2(accA[2], (u64)qb.x, wp); fma2(accA[3], (u64)qb.y, wp);
        }
        #pragma unroll
        for (int i = 0; i < 4; ++i) {
            float2 pA = upk(accA[i]);
            float2 pB = upk(accB[i]);
            h0s_t[t*8 + 2*i]     = fmaxf(pA.x + pB.x, 0.0f);
            h0s_t[t*8 + 2*i + 1] = fmaxf(pA.y + pB.y, 0.0f);
        }
    }
    __syncthreads();

    // layer 1: 512 -> 512, relu
    {
        u64 accA[4], accB[4];
        u64 bb = pk2(b1[t], b1[t]);
        u64 zz = pk2(0.0f, 0.0f);
        #pragma unroll
        for (int i = 0; i < 4; ++i) { accA[i] = bb; accB[i] = zz; }
        #pragma unroll 4
        for (int c = 0; c < 512; c += 2) {
            float wE = __ldg(w1 + (c+0)*512 + t);
            float wO = __ldg(w1 + (c+1)*512 + t);
            u64 wpE = pk2(wE, wE);
            u64 wpO = pk2(wO, wO);
            const longlong2* xpE = (const longlong2*)(h0s_t + (c+0)*8);
            const longlong2* xpO = (const longlong2*)(h0s_t + (c+1)*8);
            longlong2 qaE = xpE[0], qbE = xpE[1];
            longlong2 qaO = xpO[0], qbO = xpO[1];
            fma2(accA[0], (u64)qaE.x, wpE); fma2(accA[1], (u64)qaE.y, wpE);
            fma2(accA[2], (u64)qbE.x, wpE); fma2(accA[3], (u64)qbE.y, wpE);
            fma2(accB[0], (u64)qaO.x, wpO); fma2(accB[1], (u64)qaO.y, wpO);
            fma2(accB[2], (u64)qbO.x, wpO); fma2(accB[3], (u64)qbO.y, wpO);
        }
        #pragma unroll
        for (int i = 0; i < 4; ++i) {
            float2 pA = upk(accA[i]);
            float2 pB = upk(accB[i]);
            h1s_t[t*8 + 2*i]     = fmaxf(pA.x + pB.x, 0.0f);
            h1s_t[t*8 + 2*i + 1] = fmaxf(pA.y + pB.y, 0.0f);
        }
    }
    __syncthreads();

    // layer 2: 512 -> 3 ; warp w (0..7) handles row r = w
    {
        int wid = t >> 5, lane = t & 31;
        if (wid < 8) {
            int r = wid;
            float p0 = 0.0f, p1 = 0.0f, p2 = 0.0f;
            for (int c = lane; c < 512; c += 32) {
                float hv = h1s_t[c*8 + r];
                p0 += hv * w2[c*3 + 0];
                p1 += hv * w2[c*3 + 1];
                p2 += hv * w2[c*3 + 2];
            }
            #pragma unroll
            for (int off = 16; off > 0; off >>= 1) {
                p0 += __shfl_down_sync(0xffffffffu, p0, off);
                p1 += __shfl_down_sync(0xffffffffu, p1, off);
                p2 += __shfl_down_sync(0xffffffffu, p2, off);
            }
            if (lane == 0) {
                int node = rbase + r;
                out[node*3 + 0] = p0 + b2[0];
                out[node*3 + 1] = p1 + b2[1];
                out[node*3 + 2] = p2 + b2[2];
            }
        }
    }
}

// ---------------- launch ----------------
extern "C" void kernel_launch(void* const* d_in, const int* in_sizes, int n_in,
                              void* d_out, int out_size)
{
    const float* frac    = (const float*)d_in[0];
    const float* tim     = (const float*)d_in[1];
    const float* cell    = (const float*)d_in[2];
    const float* w_embed = (const float*)d_in[3];
    const float* r1_w0 = (const float*)d_in[4];
    const float* r1_b0 = (const float*)d_in[5];
    const float* r1_w1 = (const float*)d_in[6];
    const float* r1_b1 = (const float*)d_in[7];
    const float* r1_w2 = (const float*)d_in[8];
    const float* r1_b2 = (const float*)d_in[9];
    const float* r1_w3 = (const float*)d_in[10];
    const float* r1_b3 = (const float*)d_in[11];
    const float* mix1_l0 = (const float*)d_in[12];
    const float* mix1_l1 = (const float*)d_in[13];
    const float* mix1_l2 = (const float*)d_in[14];
    const float* r2_w0 = (const float*)d_in[15];
    const float* r2_b0 = (const float*)d_in[16];
    const float* r2_w1 = (const float*)d_in[17];
    const float* r2_b1 = (const float*)d_in[18];
    const float* r2_w2 = (const float*)d_in[19];
    const float* r2_b2 = (const float*)d_in[20];
    const float* r2_w3 = (const float*)d_in[21];
    const float* r2_b3 = (const float*)d_in[22];
    const float* mix2  = (const float*)d_in[23];
    const float* mlp_w0 = (const float*)d_in[24];
    const float* mlp_b0 = (const float*)d_in[25];
    const float* mlp_w1 = (const float*)d_in[26];
    const float* mlp_b1 = (const float*)d_in[27];
    const float* mlp_w2 = (const float*)d_in[28];
    const float* mlp_b2 = (const float*)d_in[29];

    const int SM_P1  = 9280 * 4;
    const int SM_P2  = 9088 * 4;
    const int SM_MLP = (5128 + 4096) * 4;

    cudaFuncSetAttribute(k_phase1, cudaFuncAttributeMaxDynamicSharedMemorySize, SM_P1);
    cudaFuncSetAttribute(k_phase2, cudaFuncAttributeMaxDynamicSharedMemorySize, SM_P2);
    cudaFuncSetAttribute(k_mlp,    cudaFuncAttributeMaxDynamicSharedMemorySize, SM_MLP);
    cudaFuncSetAttribute(k_phase1, cudaFuncAttributePreferredSharedMemoryCarveout, 100);
    cudaFuncSetAttribute(k_phase2, cudaFuncAttributePreferredSharedMemoryCarveout, 100);
    cudaFuncSetAttribute(k_mlp,    cudaFuncAttributePreferredSharedMemoryCarveout, 100);

    k_geom<<<NPAIR/256, 256>>>(frac, cell);
    k_phase1<<<NNODE, 128, SM_P1>>>(w_embed,
        r1_w0, r1_b0, r1_w1, r1_b1, r1_w2, r1_b2, r1_w3, r1_b3,
        mix1_l0, mix1_l1, mix1_l2);
    k_phase2<<<NNODE, 128, SM_P2>>>(
        r2_w0, r2_b0, r2_w1, r2_b1, r2_w2, r2_b2, r2_w3, r2_b3, mix2);
    k_mlp<<<NNODE/8, 512, SM_MLP>>>(tim, mlp_w0, mlp_b0, mlp_w1, mlp_b1,
        mlp_w2, mlp_b2, (float*)d_out);
}